// round 11
// baseline (speedup 1.0000x reference)
#include <cuda_runtime.h>

#define B 32
#define L 512
#define T 4096
#define D 384
#define D4 (D / 4)          // 96 float4 per row
#define RPT 8               // rows per thread
#define RPB 32              // rows per block (y-dim 4 x RPT)

// Fully fused length-regulator. One block = 32 consecutive output rows of one
// batch (T % 32 == 0 so no straddling). Warp 0 redundantly recomputes the
// per-batch duration scan (registers + shuffles) and scatters token indices
// into the block's 32-slot shared window; all 384 threads then gather with
// UNCONDITIONAL clamped loads (front-batched, MLP=8) and select-zero after.
__global__ __launch_bounds__(D4 * 4)
void lr_fused_kernel(const float4* __restrict__ seq,
                     const int*    __restrict__ dur,
                     const int*    __restrict__ mask,
                     float4*       __restrict__ out,
                     float*        __restrict__ out_tail,
                     int write_tail) {
    __shared__ int sidx[RPB];

    const int tid   = threadIdx.y * D4 + threadIdx.x;
    const int base  = blockIdx.x * RPB;       // global row
    const int b     = base >> 12;             // batch
    const int jbase = base & (T - 1);         // row within batch

    if (tid < 32) {
        // ---- init window to "invalid" ----
        sidx[tid] = -2;
        __syncwarp();

        // ---- warp-resident scan of 512 durations: 16 per lane ----
        const int lane = tid;
        const int t0   = lane * 16;
        const int* dp  = dur  + b * L + t0;
        const int* mp  = mask + b * L + t0;

        int d[16], run[16], mk[16];
        int acc = 0;
        #pragma unroll
        for (int i = 0; i < 16; ++i) {
            d[i]  = dp[i];                    // EXPAND_SCALE=1.0 -> round(d)=d
            mk[i] = mp[i];
            acc  += d[i];
            run[i] = acc;                     // inclusive within lane
        }
        // exclusive scan of lane totals across the warp
        int excl = acc;
        #pragma unroll
        for (int off = 1; off < 32; off <<= 1) {
            int n = __shfl_up_sync(0xFFFFFFFFu, excl, off);
            if (lane >= off) excl += n;
        }
        excl -= acc;

        // ---- scatter tokens intersecting [jbase, jbase+32) ----
        #pragma unroll
        for (int i = 0; i < 16; ++i) {
            const int end   = excl + run[i];  // cum[t]
            const int start = end - d[i];
            int lo = start < jbase ? jbase : start;
            int hi = end > jbase + RPB ? jbase + RPB : end;
            const int val = mk[i] ? -1 : (t0 + i);
            for (int j = lo; j < hi; ++j)
                sidx[j - jbase] = val;        // unique owner per slot
        }
    } else if (write_tail && jbase == 0) {
        // exp_dur second output: one block per batch writes it
        for (int k = tid - 32; k < L; k += (D4 * 4 - 32))
            out_tail[b * L + k] = (float)dur[b * L + k];
    }
    __syncthreads();

    // ---- gather-expand: 8 rows/thread, unconditional clamped loads ----
    const int c = threadIdx.x;                // 0..95
    const int y = threadIdx.y;                // 0..3

    int s[RPT];
    #pragma unroll
    for (int i = 0; i < RPT; ++i)
        s[i] = sidx[y + 4 * i];               // uniform per warp -> broadcast

    float4 v[RPT];
    #pragma unroll
    for (int i = 0; i < RPT; ++i) {
        const int ci = s[i] < 0 ? 0 : s[i];   // clamp: load always legal
        v[i] = seq[(b * L + ci) * D4 + c];    // 8 independent LDG.128
    }

    const float4 z = make_float4(0.f, 0.f, 0.f, 0.f);
    #pragma unroll
    for (int i = 0; i < RPT; ++i)
        if (s[i] < 0) v[i] = z;               // select, no branch around LDG

    #pragma unroll
    for (int i = 0; i < RPT; ++i)
        out[(base + y + 4 * i) * D4 + c] = v[i];
}

extern "C" void kernel_launch(void* const* d_in, const int* in_sizes, int n_in,
                              void* d_out, int out_size) {
    const float* seq  = (const float*)d_in[0];
    const int*   dur  = (const int*)d_in[1];    // int64 in ref -> int32 here
    const int*   mask = (const int*)d_in[2];    // bool in ref -> int32 here
    float* out = (float*)d_out;

    const long long main_elems = (long long)B * T * D;
    const int write_tail = (out_size >= main_elems + (long long)B * L) ? 1 : 0;

    dim3 bd(D4, 4);                             // 384 threads
    lr_fused_kernel<<<(B * T) / RPB, bd>>>((const float4*)seq, dur, mask,
                                           (float4*)out, out + main_elems,
                                           write_tail);
}

// round 12
// speedup vs baseline: 1.2212x; 1.2212x over previous
#include <cuda_runtime.h>

#define B 32
#define L 512
#define T 4096
#define D 384
#define D4 (D / 4)          // 96 float4 per row
#define RPT 8               // rows per thread in expand kernel
#define RPB (RPT * 4)       // 32 rows per block (block y-dim = 4)

// Scratch (no allocations allowed in kernel_launch)
__device__ int g_idx[B * T];

// Kernel 1: per-batch inclusive scan of durations (warp-shuffle scan) +
// scatter token index into the output-slot map, then prefill the invalid
// tail [total, T) with -1 so expand needs no bounds logic at all.
// Masked tokens scatter -1 too. Harness delivers int64 dur / bool mask as int32.
__global__ void scan_scatter_kernel(const int* __restrict__ dur,
                                    const int* __restrict__ mask,
                                    float* __restrict__ out_tail,
                                    int write_tail) {
    __shared__ int wsum[16];
    const int b    = blockIdx.x;
    const int t    = threadIdx.x;        // 0..511
    const int lane = t & 31;
    const int w    = t >> 5;             // 0..15

    const int d = dur[b * L + t];        // EXPAND_SCALE=1.0 -> round(d)=d
    int x = d;

    // inclusive warp scan
    #pragma unroll
    for (int off = 1; off < 32; off <<= 1) {
        int n = __shfl_up_sync(0xFFFFFFFFu, x, off);
        if (lane >= off) x += n;
    }
    if (lane == 31) wsum[w] = x;
    __syncthreads();

    if (w == 0 && lane < 16) {
        int y = wsum[lane];
        #pragma unroll
        for (int off = 1; off < 16; off <<= 1) {
            int n = __shfl_up_sync(0xFFFFu, y, off);
            if (lane >= off) y += n;
        }
        wsum[lane] = y;
    }
    __syncthreads();

    const int end   = x + (w > 0 ? wsum[w - 1] : 0);
    const int start = end - d;
    const int val   = mask[b * L + t] ? -1 : t;
    for (int j = start; j < end; ++j)
        g_idx[b * T + j] = val;

    // fill invalid tail [total, T) with -1
    const int total = wsum[15];
    for (int j = total + t; j < T; j += L)
        g_idx[b * T + j] = -1;

    if (write_tail)
        out_tail[b * L + t] = (float)d;   // exp_dur as second output

    // PDL: signal the dependent expand_kernel as soon as our stores are done
    cudaTriggerProgrammaticLaunchCompletion();
}

// Kernel 2: branch-free gather-expand, 8 rows/thread.
// Block (96,4) covers 32 consecutive output rows (one batch: T % 32 == 0).
// All loads unconditional (index clamped to 0), zeroed by select afterwards,
// so ptxas front-batches 8 independent LDG.E.128 per thread.
__global__ __launch_bounds__(D4 * 4)
void expand_kernel(const float4* __restrict__ seq,
                   float4* __restrict__ out) {
    const int base = blockIdx.x * RPB;
    const int c    = threadIdx.x;           // 0..95
    const int y    = threadIdx.y;           // 0..3
    const int b    = base >> 12;            // batch for all 32 rows

    int row[RPT];
    #pragma unroll
    for (int i = 0; i < RPT; ++i)
        row[i] = base + i * 4 + y;

    // Wait for scan_scatter results (PDL overlap hides launch latency)
    cudaGridDependencySynchronize();

    int idx[RPT];
    #pragma unroll
    for (int i = 0; i < RPT; ++i)
        idx[i] = g_idx[row[i]];             // complete predicate: <0 == pad

    float4 v[RPT];
    #pragma unroll
    for (int i = 0; i < RPT; ++i) {
        const int ci = idx[i] < 0 ? 0 : idx[i];   // clamp: always legal
        v[i] = seq[(b * L + ci) * D4 + c];        // 8 independent LDG.128
    }

    const float4 z = make_float4(0.f, 0.f, 0.f, 0.f);
    #pragma unroll
    for (int i = 0; i < RPT; ++i)
        if (idx[i] < 0) v[i] = z;           // select, no branch around LDG

    #pragma unroll
    for (int i = 0; i < RPT; ++i)
        out[row[i] * D4 + c] = v[i];
}

extern "C" void kernel_launch(void* const* d_in, const int* in_sizes, int n_in,
                              void* d_out, int out_size) {
    const float* seq  = (const float*)d_in[0];
    const int*   dur  = (const int*)d_in[1];    // int64 in ref -> int32 here
    const int*   mask = (const int*)d_in[2];    // bool in ref -> int32 here
    float* out = (float*)d_out;

    const long long main_elems = (long long)B * T * D;
    const int write_tail = (out_size >= main_elems + (long long)B * L) ? 1 : 0;

    scan_scatter_kernel<<<B, L>>>(dur, mask, out + main_elems, write_tail);

    // Programmatic dependent launch: expand starts early, syncs in-kernel.
    cudaLaunchConfig_t cfg = {};
    cfg.gridDim  = dim3((B * T) / RPB, 1, 1);
    cfg.blockDim = dim3(D4, 4, 1);
    cfg.dynamicSmemBytes = 0;
    cfg.stream = 0;
    cudaLaunchAttribute attr;
    attr.id = cudaLaunchAttributeProgrammaticStreamSerialization;
    attr.val.programmaticStreamSerializationAllowed = 1;
    cfg.attrs = &attr;
    cfg.numAttrs = 1;
    cudaLaunchKernelEx(&cfg, expand_kernel, (const float4*)seq, (float4*)out);
}